// round 14
// baseline (speedup 1.0000x reference)
#include <cuda_runtime.h>
#include <math.h>

#define N_AG   2048
#define HID    64
#define MED    128
#define SOC    64
#define ZK     256     // z layout: r[0:128] | e[128:192] | h[192:256]
#define NGATE  256
#define NSTEP  20
#define MAXNB  32
#define AB     16      // agents per block
#define TPB    1024
#define NBLK   (N_AG / AB)   // 128 blocks, all co-resident (1/SM)

// dynamic smem layout (bytes)
#define OFF_Z   0
#define SZ_Z    (AB * ZK * 4)                   // 16384
#define OFF_G   (OFF_Z + SZ_Z)                  // 16384
#define SZ_G    (AB * NGATE * 4)                // 16384
#define OFF_G2  (OFF_G + SZ_G)                  // 32768
#define OFF_CV  (OFF_G2 + SZ_G)                 // 49152
#define SZ_CV   (AB * HID * 4)                  // 4096
#define OFF_WSE (OFF_CV + SZ_CV)                // 53248
#define SZ_WSE  (HID * SOC * 4)                 // 16384
#define OFF_C   (OFF_WSE + SZ_WSE)              // 69632
#define SZ_C    (AB * HID * 4)                  // 4096
#define OFF_NBC (OFF_C + SZ_C)                  // 73728
#define SZ_NBC  (AB * 4)                        // 64
#define OFF_NBI (OFF_NBC + SZ_NBC)              // 73792
#define SZ_NBI  (AB * MAXNB * 4)                // 2048
#define SMEM_BYTES (OFF_NBI + SZ_NBI)           // 75840

// ---------------- device scratch (static, no runtime alloc) ----------------
__device__ float d_h[2 * N_AG * HID];          // double-buffered hidden state
__device__ float d_Wse[HID * SOC];             // collapsed social weight, K-major: [k][o]
__device__ float4 d_Wp4[128 * 128];            // gate weights, f32x2-paired:
                                               // [k2][j] = (W(2k2,j),W(2k2,j+128),W(2k2+1,j),W(2k2+1,j+128))
__device__ float d_bg[NGATE];                  // b_ih + b_hh
__device__ int   d_nbc[NSTEP * N_AG];          // neighbor counts per (t, agent)
__device__ int   d_nbi[NSTEP * N_AG * MAXNB];  // neighbor indices (ascending j)
__device__ unsigned g_bar;                     // grid-barrier arrive counter (monotonic)
__device__ unsigned g_rel;                     // grid-barrier release generation

__device__ __forceinline__ float sigm(float x)  { return __fdividef(1.f, 1.f + __expf(-x)); }
__device__ __forceinline__ float tanhft(float x){ return 1.f - __fdividef(2.f, __expf(2.f * x) + 1.f); }

__device__ __forceinline__ unsigned long long fma2(
    unsigned long long a, unsigned long long b, unsigned long long c)
{
    unsigned long long d;
    asm("fma.rn.f32x2 %0, %1, %2, %3;" : "=l"(d) : "l"(a), "l"(b), "l"(c));
    return d;
}
__device__ __forceinline__ unsigned long long dup2(float x) {
    unsigned long long r;
    asm("mov.b64 %0, {%1, %1};" : "=l"(r) : "f"(x));
    return r;
}
__device__ __forceinline__ void unpack2(unsigned long long v, float& lo, float& hi) {
    asm("mov.b64 {%0, %1}, %2;" : "=f"(lo), "=f"(hi) : "l"(v));
}

// ---------------- init: copy h0, collapse+transpose W_soc, build Wp4/bg,
// zero tail frames, reset grid barrier (must run every replay) ---------------
__global__ __launch_bounds__(256) void init_kernel(
    const float* __restrict__ h0,
    const float* __restrict__ W_soc,
    const float* __restrict__ W_ih, const float* __restrict__ W_hh,
    const float* __restrict__ b_ih, const float* __restrict__ b_hh,
    float* __restrict__ out)
{
    int i = blockIdx.x * blockDim.x + threadIdx.x;
    if (i == 0) { g_bar = 0u; g_rel = 0u; }
    if (i < N_AG * HID) d_h[i] = h0[i];
    if (i < SOC * HID) {
        int o = i & 63, k = i >> 6;
        float s = 0.f;
        #pragma unroll
        for (int w = 0; w < 9; w++) s += W_soc[o * 576 + w * 64 + k];
        d_Wse[k * 64 + o] = s;                 // K-major: lanes (o) contiguous
    }
    if (i < 128 * 128) {                       // f32x2-paired gate weights
        int k2 = i >> 7, j = i & 127;
        int k0 = 2 * k2, k1 = 2 * k2 + 1;
        int gl = j, gh = j + 128;
        float v[4];
        v[0] = (k0 < 192) ? W_ih[gl * 192 + k0] : W_hh[gl * 64 + (k0 - 192)];
        v[1] = (k0 < 192) ? W_ih[gh * 192 + k0] : W_hh[gh * 64 + (k0 - 192)];
        v[2] = (k1 < 192) ? W_ih[gl * 192 + k1] : W_hh[gl * 64 + (k1 - 192)];
        v[3] = (k1 < 192) ? W_ih[gh * 192 + k1] : W_hh[gh * 64 + (k1 - 192)];
        d_Wp4[i] = make_float4(v[0], v[1], v[2], v[3]);
    }
    if (i < NGATE) d_bg[i] = b_ih[i] + b_hh[i];
    if (i < 4 * N_AG * 2) out[NSTEP * N_AG * 2 + i] = 0.f;  // frames 20..23 = 0
}

// ---------------- neighbor precompute: grid = NSTEP*8 blocks ---------------
// Replicates ref exactly: lt = min(coords) - 1.2f; p = floor((c-lt)/0.3f);
// masked -> cell (0,0); agent i gathers cell p_i - (1,1).
__global__ __launch_bounds__(256) void nbr_kernel(
    const float* __restrict__ X, const float* __restrict__ masks)
{
    int t    = blockIdx.x >> 3;
    int pass = blockIdx.x & 7;
    __shared__ __align__(16) int keys[N_AG];
    __shared__ float rmin[16];
    const float* xt = X + t * N_AG * 2;
    int tid = threadIdx.x;

    float mnx = 3.4e38f, mny = 3.4e38f;
    for (int i = tid; i < N_AG; i += 256) {
        mnx = fminf(mnx, xt[2 * i]);
        mny = fminf(mny, xt[2 * i + 1]);
    }
    #pragma unroll
    for (int o = 16; o; o >>= 1) {
        mnx = fminf(mnx, __shfl_xor_sync(0xffffffffu, mnx, o));
        mny = fminf(mny, __shfl_xor_sync(0xffffffffu, mny, o));
    }
    if ((tid & 31) == 0) { rmin[tid >> 5] = mnx; rmin[8 + (tid >> 5)] = mny; }
    __syncthreads();
    if (tid == 0) {
        float a = rmin[0], b = rmin[8];
        for (int w = 1; w < 8; w++) { a = fminf(a, rmin[w]); b = fminf(b, rmin[8 + w]); }
        rmin[0] = a - 1.2f;  // margin = 2*N_SIZE*CELL = 1.2 (fp32)
        rmin[8] = b - 1.2f;
    }
    __syncthreads();
    float ltx = rmin[0], lty = rmin[8];

    for (int i = tid; i < N_AG; i += 256) {
        int p0 = (int)floorf(__fdiv_rn(xt[2 * i]     - ltx, 0.3f));
        int p1 = (int)floorf(__fdiv_rn(xt[2 * i + 1] - lty, 0.3f));
        if (masks[t * N_AG + i] == 0.0f) { p0 = 0; p1 = 0; }
        keys[i] = p0 * 32768 + p1;
    }
    __syncthreads();

    int i = pass * 256 + tid;
    int q = keys[i] - 32769;         // key of cell (p0-1, p1-1); masked -> negative, no match
    int cnt = 0;
    int* dst = d_nbi + (t * N_AG + i) * MAXNB;
    const int4* k4 = (const int4*)keys;
    for (int j4 = 0; j4 < N_AG / 4; j4++) {
        int4 kv = k4[j4];
        int j = j4 * 4;
        if (kv.x == q && cnt < MAXNB) dst[cnt++] = j;
        if (kv.y == q && cnt < MAXNB) dst[cnt++] = j + 1;
        if (kv.z == q && cnt < MAXNB) dst[cnt++] = j + 2;
        if (kv.w == q && cnt < MAXNB) dst[cnt++] = j + 3;
    }
    d_nbc[t * N_AG + i] = cnt;
}

// ---------------- persistent kernel: all 20 steps in one launch ------------
// grid = 128 blocks x 1024 threads; 1 block/SM -> software grid barrier safe.
// Post-barrier critical path minimized: r-stage for t+1 and the neighbor
// index prefetch happen INSIDE the barrier-wait window (they don't depend on
// other blocks' h). Per-warp acquire poll. c lives in smem all 20 steps;
// LSTM writes h straight into next step's z-tail.
__global__ __launch_bounds__(TPB, 1) void persist_kernel(
    const float* __restrict__ X, const float* __restrict__ masks,
    const float* __restrict__ h0g, const float* __restrict__ c0g,
    const float* __restrict__ W_in, const float* __restrict__ b_in,
    const float* __restrict__ b_soc,
    const float* __restrict__ W_out, const float* __restrict__ b_out,
    float* out)
{
    extern __shared__ __align__(16) char smraw[];
    float (*z_sm)[ZK]     = (float(*)[ZK])   (smraw + OFF_Z);
    float (*g_sm)[NGATE]  = (float(*)[NGATE])(smraw + OFF_G);
    float (*g2_sm)[NGATE] = (float(*)[NGATE])(smraw + OFF_G2);
    float (*cv_sm)[HID]   = (float(*)[HID])  (smraw + OFF_CV);
    float* Wse_sm         = (float*)         (smraw + OFF_WSE);
    float (*c_sm)[HID]    = (float(*)[HID])  (smraw + OFF_C);
    int*   nbc_sm         = (int*)           (smraw + OFF_NBC);
    int (*nbi_sm)[MAXNB]  = (int(*)[MAXNB])  (smraw + OFF_NBI);

    int tid = threadIdx.x;
    int ab  = blockIdx.x * AB;

    // ---- prologue: pin Wse, seed c/h, prefetch nb(0), compute r(0) ----
    for (int i = tid; i < HID * SOC; i += TPB) Wse_sm[i] = d_Wse[i];
    {
        int a = tid >> 6, d = tid & 63;
        int i = ab + a;
        c_sm[a][d] = c0g[i * HID + d];
        z_sm[a][192 + d] = h0g[i * HID + d];
    }
    if (tid < AB * MAXNB) {
        int a = tid >> 5, j = tid & 31;
        nbi_sm[a][j] = d_nbi[(0 * N_AG + ab + a) * MAXNB + j];
    }
    if (tid >= 512 && tid < 512 + AB)
        nbc_sm[tid - 512] = d_nbc[0 * N_AG + ab + (tid - 512)];
    for (int w = tid; w < AB * MED; w += TPB) {
        int a = w >> 7, o = w & 127;
        int i = ab + a;
        float v = fmaf(W_in[o * 2], X[i * 2],
                  fmaf(W_in[o * 2 + 1], X[i * 2 + 1], b_in[o]));
        z_sm[a][o] = fmaxf(v, 0.f);
    }
    __syncthreads();

    for (int t = 0; t < NSTEP; t++) {
        const float* hcur = d_h + (t & 1) * N_AG * HID;
        float*       hnxt = d_h + ((t + 1) & 1) * N_AG * HID;
        const float* mrow = masks + t * N_AG;

        // ---- social gather (cell_val) from smem-prefetched indices ----
        {
            int a = tid >> 6, d = tid & 63;
            int i = ab + a;
            int cnt = nbc_sm[a];
            float s = 0.f;
            for (int jj = 0; jj < cnt; jj++) s += hcur[nbi_sm[a][jj] * HID + d];
            cv_sm[a][d] = s * mrow[i];
        }
        __syncthreads();
        // ---- e = relu(W_eff @ cell_val + b_soc), smem weights ----
        {
            int a = tid >> 6, o = tid & 63;
            float acc = b_soc[o];
            #pragma unroll 16
            for (int k = 0; k < HID; k++)
                acc = fmaf(Wse_sm[k * 64 + o], cv_sm[a][k], acc);
            z_sm[a][MED + o] = fmaxf(acc, 0.f);
        }
        __syncthreads();
        // ---- gate GEMM (f32x2, register-packed z) ----
        {
            int gq = tid & 63;
            int kq = (tid >> 6) & 3;             // K-quarter 0..3
            int ag = tid >> 8;                   // agent group 0..3
            int a0 = ag * 4;

            unsigned long long acc2[2][4];
            #pragma unroll
            for (int q = 0; q < 2; q++)
                #pragma unroll
                for (int a = 0; a < 4; a++) acc2[q][a] = 0ull;

            #pragma unroll 2
            for (int m = 0; m < 16; m++) {
                int row = kq * 16 + m;           // k4-row, k = 4*row
                int k2  = 2 * row;
                ulonglong2 wA0 = *(const ulonglong2*)(d_Wp4 + k2 * 128 + gq);
                ulonglong2 wB0 = *(const ulonglong2*)(d_Wp4 + (k2 + 1) * 128 + gq);
                ulonglong2 wA1 = *(const ulonglong2*)(d_Wp4 + k2 * 128 + gq + 64);
                ulonglong2 wB1 = *(const ulonglong2*)(d_Wp4 + (k2 + 1) * 128 + gq + 64);
                #pragma unroll
                for (int a = 0; a < 4; a++) {
                    float4 zv = *(const float4*)&z_sm[a0 + a][4 * row];  // warp broadcast
                    unsigned long long z0 = dup2(zv.x);
                    unsigned long long z1 = dup2(zv.y);
                    unsigned long long z2 = dup2(zv.z);
                    unsigned long long z3 = dup2(zv.w);
                    acc2[0][a] = fma2(wA0.x, z0, acc2[0][a]);
                    acc2[0][a] = fma2(wA0.y, z1, acc2[0][a]);
                    acc2[0][a] = fma2(wB0.x, z2, acc2[0][a]);
                    acc2[0][a] = fma2(wB0.y, z3, acc2[0][a]);
                    acc2[1][a] = fma2(wA1.x, z0, acc2[1][a]);
                    acc2[1][a] = fma2(wA1.y, z1, acc2[1][a]);
                    acc2[1][a] = fma2(wB1.x, z2, acc2[1][a]);
                    acc2[1][a] = fma2(wB1.y, z3, acc2[1][a]);
                }
            }
            // unpack: acc2[qq][a] = (gate qq*64+gq, gate qq*64+gq+128)
            if (kq == 0) {
                #pragma unroll
                for (int q = 0; q < 2; q++) {
                    int glo = q * 64 + gq;
                    float blo = d_bg[glo], bhi = d_bg[glo + 128];
                    #pragma unroll
                    for (int a = 0; a < 4; a++) {
                        float lo, hi; unpack2(acc2[q][a], lo, hi);
                        g_sm[a0 + a][glo]       = lo + blo;
                        g_sm[a0 + a][glo + 128] = hi + bhi;
                    }
                }
            } else if (kq == 2) {
                #pragma unroll
                for (int q = 0; q < 2; q++) {
                    int glo = q * 64 + gq;
                    #pragma unroll
                    for (int a = 0; a < 4; a++) {
                        float lo, hi; unpack2(acc2[q][a], lo, hi);
                        g2_sm[a0 + a][glo]       = lo;
                        g2_sm[a0 + a][glo + 128] = hi;
                    }
                }
            }
            __syncthreads();
            if (kq == 1) {
                #pragma unroll
                for (int q = 0; q < 2; q++) {
                    int glo = q * 64 + gq;
                    #pragma unroll
                    for (int a = 0; a < 4; a++) {
                        float lo, hi; unpack2(acc2[q][a], lo, hi);
                        g_sm[a0 + a][glo]       += lo;
                        g_sm[a0 + a][glo + 128] += hi;
                    }
                }
            } else if (kq == 3) {
                #pragma unroll
                for (int q = 0; q < 2; q++) {
                    int glo = q * 64 + gq;
                    #pragma unroll
                    for (int a = 0; a < 4; a++) {
                        float lo, hi; unpack2(acc2[q][a], lo, hi);
                        g2_sm[a0 + a][glo]       += lo;
                        g2_sm[a0 + a][glo + 128] += hi;
                    }
                }
            }
        }
        __syncthreads();
        // ---- LSTM pointwise update: c in smem, h -> z-tail (+ gmem) ----
        {
            int a = tid >> 6, d = tid & 63;
            int i = ab + a;
            float gi = g_sm[a][d]       + g2_sm[a][d];
            float gf = g_sm[a][64 + d]  + g2_sm[a][64 + d];
            float gg = g_sm[a][128 + d] + g2_sm[a][128 + d];
            float go = g_sm[a][192 + d] + g2_sm[a][192 + d];
            float c = c_sm[a][d];
            c = sigm(gf) * c + sigm(gi) * tanhft(gg);
            float h = sigm(go) * tanhft(c);
            c_sm[a][d] = c;
            if (t < NSTEP - 1) hnxt[i * HID + d] = h;  // for other blocks' gathers
            z_sm[a][192 + d] = h;                      // next step's z-tail
        }
        __syncthreads();
        // ---- arrive (release; CTA-sync cumulativity covers hnxt stores) ----
        unsigned target = (unsigned)(t + 1);
        if (tid == 0 && t < NSTEP - 1) {
            unsigned prev;
            asm volatile("atom.release.gpu.add.u32 %0, [%1], %2;"
                         : "=r"(prev) : "l"(&g_bar), "r"(1u) : "memory");
            if (prev == (unsigned)NBLK * target - 1u) {
                asm volatile("st.release.gpu.u32 [%0], %1;"
                             :: "l"(&g_rel), "r"(target) : "memory");
            }
        }
        // ---- barrier-wait window: out-proj, r(t+1), nb(t+1) prefetch ----
        if (tid < 256) {
            int a  = tid >> 4;
            int oo = (tid >> 3) & 1;
            int l8 = tid & 7;
            int i  = ab + a;
            float acc = 0.f;
            #pragma unroll
            for (int k = l8 * 8; k < l8 * 8 + 8; k++)
                acc = fmaf(W_out[oo * HID + k], z_sm[a][192 + k], acc);
            acc += __shfl_xor_sync(0xffffffffu, acc, 4);
            acc += __shfl_xor_sync(0xffffffffu, acc, 2);
            acc += __shfl_xor_sync(0xffffffffu, acc, 1);
            if (l8 == 0)
                out[(t * N_AG + i) * 2 + oo] = (acc + b_out[oo]) * mrow[i];
        }
        if (t < NSTEP - 1) {
            // r(t+1): frames <=10 read X[t+1]; frames >=11 read out[t-1]
            // (out[t-1] was written two steps back -> no dependency on this
            //  step's out-projection or on other blocks)
            const float* xn = (t + 1 <= 10) ? (X + (t + 1) * N_AG * 2)
                                            : (out + (t - 1) * N_AG * 2);
            for (int w = tid; w < AB * MED; w += TPB) {
                int a = w >> 7, o = w & 127;
                int i = ab + a;
                float v = fmaf(W_in[o * 2], xn[i * 2],
                          fmaf(W_in[o * 2 + 1], xn[i * 2 + 1], b_in[o]));
                z_sm[a][o] = fmaxf(v, 0.f);
            }
            if (tid < AB * MAXNB) {
                int a = tid >> 5, j = tid & 31;
                nbi_sm[a][j] = d_nbi[((t + 1) * N_AG + ab + a) * MAXNB + j];
            }
            if (tid >= 512 && tid < 512 + AB)
                nbc_sm[tid - 512] = d_nbc[(t + 1) * N_AG + ab + (tid - 512)];
            // ---- per-warp acquire poll ----
            if ((tid & 31) == 0) {
                unsigned v;
                do {
                    asm volatile("ld.acquire.gpu.u32 %0, [%1];"
                                 : "=r"(v) : "l"(&g_rel) : "memory");
                } while (v < target);
            }
            __syncwarp();
        }
        __syncthreads();
    }
}

// ---------------- launch -----------------------------------------------------
extern "C" void kernel_launch(void* const* d_in, const int* in_sizes, int n_in,
                              void* d_out, int out_size)
{
    // W_soc has unique element count 36864; weights follow setup_inputs order around it.
    int iWsoc = -1, iX = -1, iM = -1, iH = -1, iC = -1;
    for (int i = 0; i < n_in; i++) {
        int s = in_sizes[i];
        if (s == 36864 && iWsoc < 0) iWsoc = i;   // W_soc [64,576]
        if (s == 98304 && iX < 0)    iX = i;      // X (first; Y comes later)
        if (s == 49152 && iM < 0)    iM = i;      // part_masks (before W_ih also 49152)
        if (s == 131072) { if (iH < 0) iH = i; else if (iC < 0) iC = i; }
    }
    const float* X     = (const float*)d_in[iX];
    const float* masks = (const float*)d_in[iM];
    const float* h0    = (const float*)d_in[iH];
    const float* c0    = (const float*)d_in[iC];
    const float* W_in  = (const float*)d_in[iWsoc - 2];
    const float* b_in  = (const float*)d_in[iWsoc - 1];
    const float* W_soc = (const float*)d_in[iWsoc];
    const float* b_soc = (const float*)d_in[iWsoc + 1];
    const float* W_ih  = (const float*)d_in[iWsoc + 2];
    const float* W_hh  = (const float*)d_in[iWsoc + 3];
    const float* b_ih  = (const float*)d_in[iWsoc + 4];
    const float* b_hh  = (const float*)d_in[iWsoc + 5];
    const float* W_out = (const float*)d_in[iWsoc + 6];
    const float* b_out = (const float*)d_in[iWsoc + 7];
    float* out = (float*)d_out;

    cudaFuncSetAttribute(persist_kernel,
                         cudaFuncAttributeMaxDynamicSharedMemorySize, SMEM_BYTES);

    init_kernel<<<512, 256>>>(h0, W_soc, W_ih, W_hh, b_ih, b_hh, out);
    nbr_kernel<<<NSTEP * 8, 256>>>(X, masks);
    persist_kernel<<<NBLK, TPB, SMEM_BYTES>>>(X, masks, h0, c0, W_in, b_in,
                                              b_soc, W_out, b_out, out);
}

// round 15
// speedup vs baseline: 1.1127x; 1.1127x over previous
#include <cuda_runtime.h>
#include <math.h>

#define N_AG   2048
#define HID    64
#define MED    128
#define SOC    64
#define ZK     256     // z layout: r[0:128] | e[128:192] | h[192:256]
#define NGATE  256
#define NSTEP  20
#define MAXNB  32
#define AB     16      // agents per block
#define TPB    1024
#define NBLK   (N_AG / AB)   // 128 blocks, all co-resident (1/SM)

// dynamic smem layout (bytes)
#define OFF_Z   0
#define SZ_Z    (AB * ZK * 4)                   // 16384
#define OFF_G   (OFF_Z + SZ_Z)                  // 16384
#define SZ_G    (AB * NGATE * 4)                // 16384
#define OFF_G2  (OFF_G + SZ_G)                  // 32768
#define OFF_CV  (OFF_G2 + SZ_G)                 // 49152
#define SZ_CV   (AB * HID * 4)                  // 4096
#define OFF_WSE (OFF_CV + SZ_CV)                // 53248
#define SZ_WSE  (HID * SOC * 4)                 // 16384
#define OFF_C   (OFF_WSE + SZ_WSE)              // 69632
#define SZ_C    (AB * HID * 4)                  // 4096
#define OFF_NBC (OFF_C + SZ_C)                  // 73728
#define SZ_NBC  (AB * 4)                        // 64
#define OFF_NBI (OFF_NBC + SZ_NBC)              // 73792
#define SZ_NBI  (AB * MAXNB * 4)                // 2048
#define SMEM_BYTES (OFF_NBI + SZ_NBI)           // 75840

// ---------------- device scratch (static, no runtime alloc) ----------------
__device__ float d_h[2 * N_AG * HID];          // double-buffered hidden state
__device__ float d_Wse[HID * SOC];             // collapsed social weight, K-major: [k][o]
__device__ float4 d_Wp4[128 * 128];            // gate weights, f32x2-paired:
                                               // [k2][j] = (W(2k2,j),W(2k2,j+128),W(2k2+1,j),W(2k2+1,j+128))
__device__ float d_bg[NGATE];                  // b_ih + b_hh
__device__ int   d_nbc[NSTEP * N_AG];          // neighbor counts per (t, agent)
__device__ int   d_nbi[NSTEP * N_AG * MAXNB];  // neighbor indices (ascending j)
__device__ unsigned g_bar;                     // grid-barrier arrive counter (monotonic)
__device__ unsigned g_rel;                     // grid-barrier release generation

__device__ __forceinline__ float sigm(float x)  { return __fdividef(1.f, 1.f + __expf(-x)); }
__device__ __forceinline__ float tanhft(float x){ return 1.f - __fdividef(2.f, __expf(2.f * x) + 1.f); }

__device__ __forceinline__ unsigned long long fma2(
    unsigned long long a, unsigned long long b, unsigned long long c)
{
    unsigned long long d;
    asm("fma.rn.f32x2 %0, %1, %2, %3;" : "=l"(d) : "l"(a), "l"(b), "l"(c));
    return d;
}
__device__ __forceinline__ unsigned long long dup2(float x) {
    unsigned long long r;
    asm("mov.b64 %0, {%1, %1};" : "=l"(r) : "f"(x));
    return r;
}
__device__ __forceinline__ void unpack2(unsigned long long v, float& lo, float& hi) {
    asm("mov.b64 {%0, %1}, %2;" : "=f"(lo), "=f"(hi) : "l"(v));
}

// ---------------- init: copy h0, collapse+transpose W_soc, build Wp4/bg,
// zero tail frames, reset grid barrier (must run every replay) ---------------
__global__ __launch_bounds__(256) void init_kernel(
    const float* __restrict__ h0,
    const float* __restrict__ W_soc,
    const float* __restrict__ W_ih, const float* __restrict__ W_hh,
    const float* __restrict__ b_ih, const float* __restrict__ b_hh,
    float* __restrict__ out)
{
    int i = blockIdx.x * blockDim.x + threadIdx.x;
    if (i == 0) { g_bar = 0u; g_rel = 0u; }
    if (i < N_AG * HID) d_h[i] = h0[i];
    if (i < SOC * HID) {
        int o = i & 63, k = i >> 6;
        float s = 0.f;
        #pragma unroll
        for (int w = 0; w < 9; w++) s += W_soc[o * 576 + w * 64 + k];
        d_Wse[k * 64 + o] = s;                 // K-major: lanes (o) contiguous
    }
    if (i < 128 * 128) {                       // f32x2-paired gate weights
        int k2 = i >> 7, j = i & 127;
        int k0 = 2 * k2, k1 = 2 * k2 + 1;
        int gl = j, gh = j + 128;
        float v[4];
        v[0] = (k0 < 192) ? W_ih[gl * 192 + k0] : W_hh[gl * 64 + (k0 - 192)];
        v[1] = (k0 < 192) ? W_ih[gh * 192 + k0] : W_hh[gh * 64 + (k0 - 192)];
        v[2] = (k1 < 192) ? W_ih[gl * 192 + k1] : W_hh[gl * 64 + (k1 - 192)];
        v[3] = (k1 < 192) ? W_ih[gh * 192 + k1] : W_hh[gh * 64 + (k1 - 192)];
        d_Wp4[i] = make_float4(v[0], v[1], v[2], v[3]);
    }
    if (i < NGATE) d_bg[i] = b_ih[i] + b_hh[i];
    if (i < 4 * N_AG * 2) out[NSTEP * N_AG * 2 + i] = 0.f;  // frames 20..23 = 0
}

// ---------------- neighbor precompute: grid = NSTEP*8 blocks ---------------
// Replicates ref exactly: lt = min(coords) - 1.2f; p = floor((c-lt)/0.3f);
// masked -> cell (0,0); agent i gathers cell p_i - (1,1).
__global__ __launch_bounds__(256) void nbr_kernel(
    const float* __restrict__ X, const float* __restrict__ masks)
{
    int t    = blockIdx.x >> 3;
    int pass = blockIdx.x & 7;
    __shared__ __align__(16) int keys[N_AG];
    __shared__ float rmin[16];
    const float* xt = X + t * N_AG * 2;
    int tid = threadIdx.x;

    float mnx = 3.4e38f, mny = 3.4e38f;
    for (int i = tid; i < N_AG; i += 256) {
        mnx = fminf(mnx, xt[2 * i]);
        mny = fminf(mny, xt[2 * i + 1]);
    }
    #pragma unroll
    for (int o = 16; o; o >>= 1) {
        mnx = fminf(mnx, __shfl_xor_sync(0xffffffffu, mnx, o));
        mny = fminf(mny, __shfl_xor_sync(0xffffffffu, mny, o));
    }
    if ((tid & 31) == 0) { rmin[tid >> 5] = mnx; rmin[8 + (tid >> 5)] = mny; }
    __syncthreads();
    if (tid == 0) {
        float a = rmin[0], b = rmin[8];
        for (int w = 1; w < 8; w++) { a = fminf(a, rmin[w]); b = fminf(b, rmin[8 + w]); }
        rmin[0] = a - 1.2f;  // margin = 2*N_SIZE*CELL = 1.2 (fp32)
        rmin[8] = b - 1.2f;
    }
    __syncthreads();
    float ltx = rmin[0], lty = rmin[8];

    for (int i = tid; i < N_AG; i += 256) {
        int p0 = (int)floorf(__fdiv_rn(xt[2 * i]     - ltx, 0.3f));
        int p1 = (int)floorf(__fdiv_rn(xt[2 * i + 1] - lty, 0.3f));
        if (masks[t * N_AG + i] == 0.0f) { p0 = 0; p1 = 0; }
        keys[i] = p0 * 32768 + p1;
    }
    __syncthreads();

    int i = pass * 256 + tid;
    int q = keys[i] - 32769;         // key of cell (p0-1, p1-1); masked -> negative, no match
    int cnt = 0;
    int* dst = d_nbi + (t * N_AG + i) * MAXNB;
    const int4* k4 = (const int4*)keys;
    for (int j4 = 0; j4 < N_AG / 4; j4++) {
        int4 kv = k4[j4];
        int j = j4 * 4;
        if (kv.x == q && cnt < MAXNB) dst[cnt++] = j;
        if (kv.y == q && cnt < MAXNB) dst[cnt++] = j + 1;
        if (kv.z == q && cnt < MAXNB) dst[cnt++] = j + 2;
        if (kv.w == q && cnt < MAXNB) dst[cnt++] = j + 3;
    }
    d_nbc[t * N_AG + i] = cnt;
}

// ---------------- persistent kernel: all 20 steps in one launch ------------
// grid = 128 blocks x 1024 threads; 1 block/SM -> software grid barrier safe.
// Structure = round-12 winner (317us): merged gather+r phase, tid0-only
// acquire poll, out-projection in the arrive->poll window. Added: nb(t+1)
// count/index prefetch into smem during the same window (threads 256..783,
// disjoint from out-proj threads 0..255), removing the dependent
// cnt->idx->h LDG chain from the post-barrier critical path.
__global__ __launch_bounds__(TPB, 1) void persist_kernel(
    const float* __restrict__ X, const float* __restrict__ masks,
    const float* __restrict__ h0g, const float* __restrict__ c0g,
    const float* __restrict__ W_in, const float* __restrict__ b_in,
    const float* __restrict__ b_soc,
    const float* __restrict__ W_out, const float* __restrict__ b_out,
    float* out)
{
    extern __shared__ __align__(16) char smraw[];
    float (*z_sm)[ZK]     = (float(*)[ZK])   (smraw + OFF_Z);
    float (*g_sm)[NGATE]  = (float(*)[NGATE])(smraw + OFF_G);
    float (*g2_sm)[NGATE] = (float(*)[NGATE])(smraw + OFF_G2);
    float (*cv_sm)[HID]   = (float(*)[HID])  (smraw + OFF_CV);
    float* Wse_sm         = (float*)         (smraw + OFF_WSE);
    float (*c_sm)[HID]    = (float(*)[HID])  (smraw + OFF_C);
    int*   nbc_sm         = (int*)           (smraw + OFF_NBC);
    int (*nbi_sm)[MAXNB]  = (int(*)[MAXNB])  (smraw + OFF_NBI);

    int tid = threadIdx.x;
    int ab  = blockIdx.x * AB;

    // one-time: pin social weights, seed c and the z-tail (h), prefetch nb(0)
    for (int i = tid; i < HID * SOC; i += TPB) Wse_sm[i] = d_Wse[i];
    {
        int a = tid >> 6, d = tid & 63;
        int i = ab + a;
        c_sm[a][d] = c0g[i * HID + d];
        z_sm[a][192 + d] = h0g[i * HID + d];
    }
    if (tid < AB * MAXNB) {
        int a = tid >> 5, j = tid & 31;
        nbi_sm[a][j] = d_nbi[(ab + a) * MAXNB + j];
    }
    if (tid >= 768 && tid < 768 + AB)
        nbc_sm[tid - 768] = d_nbc[ab + (tid - 768)];
    // (covered by the per-step __syncthreads before first reads)

    for (int t = 0; t < NSTEP; t++) {
        const float* hcur = d_h + (t & 1) * N_AG * HID;
        float*       hnxt = d_h + ((t + 1) & 1) * N_AG * HID;
        const float* mrow = masks + t * N_AG;
        // ref: frames 0..10 feed X[t]; frames >=11 feed out[t-2]
        const float* xin = (t <= 10) ? (X + t * N_AG * 2) : (out + (t - 2) * N_AG * 2);

        // ---- social gather (cell_val) from smem-prefetched indices ----
        {
            int a = tid >> 6, d = tid & 63;
            int i = ab + a;
            int cnt = nbc_sm[a];
            float s = 0.f;
            for (int jj = 0; jj < cnt; jj++) s += hcur[nbi_sm[a][jj] * HID + d];
            cv_sm[a][d] = s * mrow[i];
        }
        // ---- r = relu(W_in @ x + b_in): 2048 items (merged with gather) ----
        for (int w = tid; w < AB * MED; w += TPB) {
            int a = w >> 7, o = w & 127;
            int i = ab + a;
            float v = fmaf(W_in[o * 2], xin[i * 2],
                      fmaf(W_in[o * 2 + 1], xin[i * 2 + 1], b_in[o]));
            z_sm[a][o] = fmaxf(v, 0.f);
        }
        __syncthreads();
        // ---- e = relu(W_eff @ cell_val + b_soc), smem weights ----
        {
            int a = tid >> 6, o = tid & 63;
            float acc = b_soc[o];
            #pragma unroll 16
            for (int k = 0; k < HID; k++)
                acc = fmaf(Wse_sm[k * 64 + o], cv_sm[a][k], acc);
            z_sm[a][MED + o] = fmaxf(acc, 0.f);
        }
        __syncthreads();
        // ---- gate GEMM (f32x2, register-packed z) ----
        {
            int gq = tid & 63;
            int kq = (tid >> 6) & 3;             // K-quarter 0..3
            int ag = tid >> 8;                   // agent group 0..3
            int a0 = ag * 4;

            unsigned long long acc2[2][4];
            #pragma unroll
            for (int q = 0; q < 2; q++)
                #pragma unroll
                for (int a = 0; a < 4; a++) acc2[q][a] = 0ull;

            #pragma unroll 2
            for (int m = 0; m < 16; m++) {
                int row = kq * 16 + m;           // k4-row, k = 4*row
                int k2  = 2 * row;
                ulonglong2 wA0 = *(const ulonglong2*)(d_Wp4 + k2 * 128 + gq);
                ulonglong2 wB0 = *(const ulonglong2*)(d_Wp4 + (k2 + 1) * 128 + gq);
                ulonglong2 wA1 = *(const ulonglong2*)(d_Wp4 + k2 * 128 + gq + 64);
                ulonglong2 wB1 = *(const ulonglong2*)(d_Wp4 + (k2 + 1) * 128 + gq + 64);
                #pragma unroll
                for (int a = 0; a < 4; a++) {
                    float4 zv = *(const float4*)&z_sm[a0 + a][4 * row];  // warp broadcast
                    unsigned long long z0 = dup2(zv.x);
                    unsigned long long z1 = dup2(zv.y);
                    unsigned long long z2 = dup2(zv.z);
                    unsigned long long z3 = dup2(zv.w);
                    acc2[0][a] = fma2(wA0.x, z0, acc2[0][a]);
                    acc2[0][a] = fma2(wA0.y, z1, acc2[0][a]);
                    acc2[0][a] = fma2(wB0.x, z2, acc2[0][a]);
                    acc2[0][a] = fma2(wB0.y, z3, acc2[0][a]);
                    acc2[1][a] = fma2(wA1.x, z0, acc2[1][a]);
                    acc2[1][a] = fma2(wA1.y, z1, acc2[1][a]);
                    acc2[1][a] = fma2(wB1.x, z2, acc2[1][a]);
                    acc2[1][a] = fma2(wB1.y, z3, acc2[1][a]);
                }
            }
            // unpack: acc2[qq][a] = (gate qq*64+gq, gate qq*64+gq+128)
            if (kq == 0) {
                #pragma unroll
                for (int q = 0; q < 2; q++) {
                    int glo = q * 64 + gq;
                    float blo = d_bg[glo], bhi = d_bg[glo + 128];
                    #pragma unroll
                    for (int a = 0; a < 4; a++) {
                        float lo, hi; unpack2(acc2[q][a], lo, hi);
                        g_sm[a0 + a][glo]       = lo + blo;
                        g_sm[a0 + a][glo + 128] = hi + bhi;
                    }
                }
            } else if (kq == 2) {
                #pragma unroll
                for (int q = 0; q < 2; q++) {
                    int glo = q * 64 + gq;
                    #pragma unroll
                    for (int a = 0; a < 4; a++) {
                        float lo, hi; unpack2(acc2[q][a], lo, hi);
                        g2_sm[a0 + a][glo]       = lo;
                        g2_sm[a0 + a][glo + 128] = hi;
                    }
                }
            }
            __syncthreads();
            if (kq == 1) {
                #pragma unroll
                for (int q = 0; q < 2; q++) {
                    int glo = q * 64 + gq;
                    #pragma unroll
                    for (int a = 0; a < 4; a++) {
                        float lo, hi; unpack2(acc2[q][a], lo, hi);
                        g_sm[a0 + a][glo]       += lo;
                        g_sm[a0 + a][glo + 128] += hi;
                    }
                }
            } else if (kq == 3) {
                #pragma unroll
                for (int q = 0; q < 2; q++) {
                    int glo = q * 64 + gq;
                    #pragma unroll
                    for (int a = 0; a < 4; a++) {
                        float lo, hi; unpack2(acc2[q][a], lo, hi);
                        g2_sm[a0 + a][glo]       += lo;
                        g2_sm[a0 + a][glo + 128] += hi;
                    }
                }
            }
        }
        __syncthreads();
        // ---- LSTM pointwise update: c in smem, h -> z-tail (+ gmem) ----
        {
            int a = tid >> 6, d = tid & 63;
            int i = ab + a;
            float gi = g_sm[a][d]       + g2_sm[a][d];
            float gf = g_sm[a][64 + d]  + g2_sm[a][64 + d];
            float gg = g_sm[a][128 + d] + g2_sm[a][128 + d];
            float go = g_sm[a][192 + d] + g2_sm[a][192 + d];
            float c = c_sm[a][d];
            c = sigm(gf) * c + sigm(gi) * tanhft(gg);
            float h = sigm(go) * tanhft(c);
            c_sm[a][d] = c;
            if (t < NSTEP - 1) hnxt[i * HID + d] = h;  // for other blocks' gathers
            z_sm[a][192 + d] = h;                      // next step's z-tail
        }
        __syncthreads();
        // ---- arrive early (release covers hnxt via CTA-sync cumulativity) ----
        unsigned target = (unsigned)(t + 1);
        if (tid == 0 && t < NSTEP - 1) {
            unsigned prev;
            asm volatile("atom.release.gpu.add.u32 %0, [%1], %2;"
                         : "=r"(prev) : "l"(&g_bar), "r"(1u) : "memory");
            if (prev == (unsigned)NBLK * target - 1u) {
                asm volatile("st.release.gpu.u32 [%0], %1;"
                             :: "l"(&g_rel), "r"(target) : "memory");
            }
        }
        // ---- window: out-projection (tid<256) + nb(t+1) prefetch (256..783) ----
        if (tid < 256) {
            int a  = tid >> 4;
            int oo = (tid >> 3) & 1;
            int l8 = tid & 7;
            int i  = ab + a;
            float acc = 0.f;
            #pragma unroll
            for (int k = l8 * 8; k < l8 * 8 + 8; k++)
                acc = fmaf(W_out[oo * HID + k], z_sm[a][192 + k], acc);
            acc += __shfl_xor_sync(0xffffffffu, acc, 4);
            acc += __shfl_xor_sync(0xffffffffu, acc, 2);
            acc += __shfl_xor_sync(0xffffffffu, acc, 1);
            if (l8 == 0)
                out[(t * N_AG + i) * 2 + oo] = (acc + b_out[oo]) * mrow[i];
        } else if (t < NSTEP - 1) {
            int pt = tid - 256;
            if (pt < AB * MAXNB) {               // threads 256..767
                int a = pt >> 5, j = pt & 31;
                nbi_sm[a][j] = d_nbi[((t + 1) * N_AG + ab + a) * MAXNB + j];
            } else if (pt < AB * MAXNB + AB) {   // threads 768..783
                int a = pt - AB * MAXNB;
                nbc_sm[a] = d_nbc[(t + 1) * N_AG + ab + a];
            }
        }
        // ---- wait for all blocks' hnxt (acquire, tid0 only) ----
        if (tid == 0 && t < NSTEP - 1) {
            unsigned v;
            do {
                asm volatile("ld.acquire.gpu.u32 %0, [%1];"
                             : "=r"(v) : "l"(&g_rel) : "memory");
            } while (v < target);
        }
        __syncthreads();
    }
}

// ---------------- launch -----------------------------------------------------
extern "C" void kernel_launch(void* const* d_in, const int* in_sizes, int n_in,
                              void* d_out, int out_size)
{
    // W_soc has unique element count 36864; weights follow setup_inputs order around it.
    int iWsoc = -1, iX = -1, iM = -1, iH = -1, iC = -1;
    for (int i = 0; i < n_in; i++) {
        int s = in_sizes[i];
        if (s == 36864 && iWsoc < 0) iWsoc = i;   // W_soc [64,576]
        if (s == 98304 && iX < 0)    iX = i;      // X (first; Y comes later)
        if (s == 49152 && iM < 0)    iM = i;      // part_masks (before W_ih also 49152)
        if (s == 131072) { if (iH < 0) iH = i; else if (iC < 0) iC = i; }
    }
    const float* X     = (const float*)d_in[iX];
    const float* masks = (const float*)d_in[iM];
    const float* h0    = (const float*)d_in[iH];
    const float* c0    = (const float*)d_in[iC];
    const float* W_in  = (const float*)d_in[iWsoc - 2];
    const float* b_in  = (const float*)d_in[iWsoc - 1];
    const float* W_soc = (const float*)d_in[iWsoc];
    const float* b_soc = (const float*)d_in[iWsoc + 1];
    const float* W_ih  = (const float*)d_in[iWsoc + 2];
    const float* W_hh  = (const float*)d_in[iWsoc + 3];
    const float* b_ih  = (const float*)d_in[iWsoc + 4];
    const float* b_hh  = (const float*)d_in[iWsoc + 5];
    const float* W_out = (const float*)d_in[iWsoc + 6];
    const float* b_out = (const float*)d_in[iWsoc + 7];
    float* out = (float*)d_out;

    cudaFuncSetAttribute(persist_kernel,
                         cudaFuncAttributeMaxDynamicSharedMemorySize, SMEM_BYTES);

    init_kernel<<<512, 256>>>(h0, W_soc, W_ih, W_hh, b_ih, b_hh, out);
    nbr_kernel<<<NSTEP * 8, 256>>>(X, masks);
    persist_kernel<<<NBLK, TPB, SMEM_BYTES>>>(X, masks, h0, c0, W_in, b_in,
                                              b_soc, W_out, b_out, out);
}